// round 1
// baseline (speedup 1.0000x reference)
#include <cuda_runtime.h>
#include <math.h>

#define H    16
#define S    2048
#define D    64
#define DIMM 1024
#define SCMP 128
#define GDIM 48

// ---------------- scratch (static device allocations) ----------------
__device__ float d_q[H*S*D];
__device__ float d_k[H*S*D];
__device__ float d_v[H*S*D];
__device__ float d_g1[S*512];
__device__ float d_gate[S*GDIM];
__device__ float d_kc[H*SCMP*D];
__device__ float d_vc[H*SCMP*D];
__device__ float d_oacc[S*DIMM];
__device__ unsigned d_bm[H*S];

enum { EPI_NONE=0, EPI_SILU=1, EPI_SIGMOID=2, EPI_HEAD=3 };

// ---------------- generic tiled fp32 GEMM: C = epi(A[M,K] @ B[K,N]) ----------------
__global__ void gemm128(const float* __restrict__ A, const float* __restrict__ B,
                        float* __restrict__ C, int M, int N, int K, int epi)
{
    __shared__ __align__(16) float As[8*128];
    __shared__ __align__(16) float Bs[8*128];
    int tid = threadIdx.x;
    int tx = tid & 15, ty = tid >> 4;
    int m0 = blockIdx.y * 128, n0 = blockIdx.x * 128;

    float acc[8][8];
    #pragma unroll
    for (int i=0;i<8;i++)
        #pragma unroll
        for (int j=0;j<8;j++) acc[i][j]=0.f;

    for (int k0=0;k0<K;k0+=8) {
        #pragma unroll
        for (int r=0;r<4;r++){
            int li = tid + r*256;
            int m = li>>3, kk = li&7;
            int gm = m0+m, gk = k0+kk;
            float v = 0.f;
            if (gm < M) v = A[(long)gm*K + gk];
            As[kk*128+m]=v;
        }
        #pragma unroll
        for (int r=0;r<4;r++){
            int li = tid + r*256;
            int kk = li>>7, n = li&127;
            int gk = k0+kk, gn = n0+n;
            float v = 0.f;
            if (gn < N) v = B[(long)gk*N + gn];
            Bs[kk*128+n]=v;
        }
        __syncthreads();
        #pragma unroll
        for (int kk=0;kk<8;kk++){
            float4 a0 = *(const float4*)&As[kk*128 + ty*8];
            float4 a1 = *(const float4*)&As[kk*128 + ty*8 + 4];
            float4 b0 = *(const float4*)&Bs[kk*128 + tx*8];
            float4 b1 = *(const float4*)&Bs[kk*128 + tx*8 + 4];
            float av[8] = {a0.x,a0.y,a0.z,a0.w,a1.x,a1.y,a1.z,a1.w};
            float bv[8] = {b0.x,b0.y,b0.z,b0.w,b1.x,b1.y,b1.z,b1.w};
            #pragma unroll
            for (int i=0;i<8;i++)
                #pragma unroll
                for (int j=0;j<8;j++) acc[i][j] += av[i]*bv[j];
        }
        __syncthreads();
    }
    #pragma unroll
    for (int i=0;i<8;i++){
        int gm = m0 + ty*8 + i;
        if (gm >= M) continue;
        #pragma unroll
        for (int j=0;j<8;j++){
            int gn = n0 + tx*8 + j;
            if (gn >= N) continue;
            float vv = acc[i][j];
            if (epi==EPI_SILU)         vv = vv/(1.f+__expf(-vv));
            else if (epi==EPI_SIGMOID) vv = 1.f/(1.f+__expf(-vv));
            if (epi==EPI_HEAD) C[((gn>>6)*S + gm)*D + (gn&63)] = vv;
            else               C[(long)gm*N + gn] = vv;
        }
    }
}

// ---------------- compression Phi: [B,H,S,D] -> [H,SCMP,D] ----------------
__global__ void compress_kernel(const float* __restrict__ src, const float* __restrict__ pe,
                                const float* __restrict__ down, const float* __restrict__ stop,
                                float* __restrict__ dst)
{
    __shared__ float bufA[32*64];
    __shared__ float bufB[16*64];
    int w = blockIdx.x, h = blockIdx.y, d = threadIdx.x;
    if (w == 0){ dst[(h*SCMP + 0)*D + d] = 0.f; return; }
    int s0 = (w-1)*16;
    #pragma unroll
    for (int i=0;i<32;i++)
        bufA[i*64+d] = src[(h*S + s0+i)*D + d] + pe[i*64+d];
    __syncthreads();

    float* cur = bufA; float* nxt = bufB;
    int L = 32;
    for (int lev=0; lev<5; lev++){
        int P = L >> 1;
        float accs[16];
        #pragma unroll
        for (int p=0;p<16;p++) accs[p]=0.f;
        const float* W = down + lev*(128*64);
        for (int j=0;j<128;j++){
            float wv = W[j*64 + d];
            int base = (j>>6)*64 + (j&63);
            #pragma unroll
            for (int p=0;p<16;p++)
                if (p < P) accs[p] += cur[p*128 + base]*wv;
        }
        for (int p=0;p<P;p++){
            float xx = accs[p];
            nxt[p*64+d] = xx / (1.f + __expf(-xx));   // silu
        }
        __syncthreads();
        float* t = cur; cur = nxt; nxt = t;
        L = P;
    }
    float a = 0.f;
    #pragma unroll
    for (int j=0;j<64;j++) a += cur[j]*stop[j*64+d];
    dst[(h*SCMP + w)*D + d] = a;
}

// ---------------- compressed-branch attention + conv + top-k selection ----------------
// grid (S/8, H), block 128. Produces o_acc = g0*o_cmp, and d_bm block bitmasks.
__global__ void cmp_attn(float scale)
{
    extern __shared__ float csm[];
    float* kc_s = csm;             // 8192
    float* vc_s = kc_s + 8192;     // 8192
    float* q_s  = vc_s + 8192;     // 64
    float* p_sm = q_s + 64;        // 128
    float* ps   = p_sm + 128;      // 32
    float* red  = ps + 32;         // 4

    int h = blockIdx.y;
    int tid = threadIdx.x;
    int lane = tid & 31, wid = tid >> 5;

    for (int i=tid;i<8192;i+=128){ kc_s[i]=d_kc[h*8192+i]; vc_s[i]=d_vc[h*8192+i]; }

    for (int qi=0;qi<8;qi++){
        int q = blockIdx.x*8 + qi;
        __syncthreads();
        if (tid < 64) q_s[tid] = d_q[(h*S + q)*D + tid];
        __syncthreads();

        int r = q >> 4;
        float sc = -INFINITY;
        {
            bool ok = (tid <= r-1) || (tid==0 && r<32);
            if (ok){
                float a=0.f;
                #pragma unroll
                for (int dd=0;dd<64;dd++) a += q_s[dd]*kc_s[tid*64+dd];
                sc = a*scale;
            }
        }
        float v = sc;
        #pragma unroll
        for (int off=16;off;off>>=1) v = fmaxf(v, __shfl_xor_sync(0xffffffffu,v,off));
        if (lane==0) red[wid]=v;
        __syncthreads();
        float m = fmaxf(fmaxf(red[0],red[1]),fmaxf(red[2],red[3]));
        float p = __expf(sc - m);                 // masked (-inf) -> 0
        p_sm[tid] = p;
        __syncthreads();
        float sv = p;
        #pragma unroll
        for (int off=16;off;off>>=1) sv += __shfl_xor_sync(0xffffffffu,sv,off);
        if (lane==0) red[wid]=sv;
        __syncthreads();
        float l = red[0]+red[1]+red[2]+red[3];

        // conv1d [1,2,2,2,1] stride 4 pad 1, then stable rank top-16 (warp 3)
        if (wid == 3){
            int n = lane;
            float a = 2.f*(p_sm[4*n] + p_sm[4*n+1] + p_sm[4*n+2]) + p_sm[4*n+3];
            if (4*n-1 >= 0) a += p_sm[4*n-1];
            ps[n] = a;
            __syncwarp();
            float mv = ps[n];
            int cnt = 0;
            #pragma unroll
            for (int i2=0;i2<32;i2++){
                float vi = ps[i2];
                cnt += (vi > mv) || (vi == mv && i2 < n);
            }
            bool sel = (cnt < 16) && (n < (q >> 6));
            unsigned msk = __ballot_sync(0xffffffffu, sel);
            if (lane==0) d_bm[h*S + q] = msk;
        }
        // o_cmp, weighted by gate 0
        if (tid < 64){
            float a = 0.f;
            for (int j=0;j<128;j++) a += p_sm[j]*vc_s[j*64+tid];
            float g0 = d_gate[q*GDIM + h*3 + 0];
            d_oacc[q*DIMM + h*64 + tid] = g0 * (a / l);
        }
    }
}

// ---------------- flash-style sparse attention (MODE 0 = selection, 1 = sliding) ----------------
// grid (S/64, H), block 256 (16x16 threads, 4x4 microtile). Accumulates g*o into d_oacc.
template<int MODE>
__global__ void attn_flash(float scale)
{
    extern __shared__ float fsm[];
    float* q_s  = fsm;             // 64*65
    float* kv_s = q_s  + 64*65;
    float* p_s  = kv_s + 64*65;
    float* m_s  = p_s  + 64*65;    // 64
    float* l_s  = m_s + 64;        // 64
    unsigned* msk_s = (unsigned*)(l_s + 64);  // 64
    unsigned* u_s   = msk_s + 64;             // 1

    int tq = blockIdx.x, h = blockIdx.y;
    int q0 = tq*64;
    int tid = threadIdx.x;
    int tx = tid & 15, ty = tid >> 4;

    #pragma unroll
    for (int r2=0;r2<16;r2++){
        int li = tid + r2*256;
        int row = li>>6, col = li&63;
        q_s[row*65+col] = d_q[(h*S + q0+row)*D + col];
    }
    if (tid < 64){
        m_s[tid] = -INFINITY; l_s[tid] = 0.f;
        if (MODE==0) msk_s[tid] = d_bm[h*S + q0 + tid];
    }
    __syncthreads();

    unsigned uni = 0xFFFFFFFFu;
    if (MODE==0){
        if (tid==0){
            unsigned u=0;
            for (int i=0;i<64;i++) u |= msk_s[i];
            u_s[0]=u;
        }
        __syncthreads();
        uni = u_s[0];
        if (uni == 0u) return;     // block-uniform exit (adds exactly zero)
    }

    int nlo, nhi;
    if (MODE==0){ nlo=0; nhi=tq; }
    else { nlo = tq-8; if (nlo<0) nlo=0; nhi = tq+1; }

    float acc[4][4];
    #pragma unroll
    for (int i=0;i<4;i++)
        #pragma unroll
        for (int j=0;j<4;j++) acc[i][j]=0.f;

    for (int n=nlo;n<nhi;n++){
        if (MODE==0 && !((uni>>n)&1u)) continue;

        #pragma unroll
        for (int r2=0;r2<16;r2++){
            int li = tid + r2*256;
            int row = li>>6, col = li&63;
            kv_s[row*65+col] = d_k[(h*S + n*64+row)*D + col];
        }
        __syncthreads();

        float s[4][4];
        #pragma unroll
        for (int i=0;i<4;i++)
            #pragma unroll
            for (int j=0;j<4;j++) s[i][j]=0.f;
        #pragma unroll 8
        for (int dd=0;dd<64;dd++){
            float qv[4], kv[4];
            #pragma unroll
            for (int i=0;i<4;i++) qv[i]=q_s[(ty*4+i)*65 + dd];
            #pragma unroll
            for (int j=0;j<4;j++) kv[j]=kv_s[(tx*4+j)*65 + dd];
            #pragma unroll
            for (int i=0;i<4;i++)
                #pragma unroll
                for (int j=0;j<4;j++) s[i][j] += qv[i]*kv[j];
        }

        float amn[4], anl[4];
        #pragma unroll
        for (int i=0;i<4;i++){
            int qi = ty*4+i;
            int qg = q0 + qi;
            unsigned mbits = (MODE==0) ? msk_s[qi] : 0u;
            float rm = -INFINITY;
            #pragma unroll
            for (int j=0;j<4;j++){
                bool ok;
                if (MODE==0) ok = (mbits>>n)&1u;
                else { int t = n*64 + tx*4 + j; ok = (t <= qg) && (qg - t <= 512); }
                float val = ok ? s[i][j]*scale : -INFINITY;
                s[i][j]=val;
                rm = fmaxf(rm, val);
            }
            #pragma unroll
            for (int off=8;off;off>>=1) rm = fmaxf(rm, __shfl_xor_sync(0xffffffffu, rm, off));
            float mo = m_s[qi];
            float mn = fmaxf(mo, rm);
            float alpha = 1.f, ts = 0.f;
            if (mn == -INFINITY){
                #pragma unroll
                for (int j=0;j<4;j++) s[i][j]=0.f;
            } else {
                alpha = __expf(mo - mn);  // mo=-inf -> 0
                #pragma unroll
                for (int j=0;j<4;j++){ float pp = __expf(s[i][j]-mn); s[i][j]=pp; ts += pp; }
            }
            #pragma unroll
            for (int off=8;off;off>>=1) ts += __shfl_xor_sync(0xffffffffu, ts, off);
            #pragma unroll
            for (int j=0;j<4;j++) p_s[qi*65 + tx*4 + j] = s[i][j];
            #pragma unroll
            for (int j=0;j<4;j++) acc[i][j] *= alpha;
            amn[i]=mn; anl[i]=l_s[qi]*alpha + ts;
        }
        __syncthreads();
        if (tx==0){
            #pragma unroll
            for (int i=0;i<4;i++){ m_s[ty*4+i]=amn[i]; l_s[ty*4+i]=anl[i]; }
        }
        // V tile (reuses kv_s; all K reads finished before the sync above)
        #pragma unroll
        for (int r2=0;r2<16;r2++){
            int li = tid + r2*256;
            int row = li>>6, col = li&63;
            kv_s[row*65+col] = d_v[(h*S + n*64+row)*D + col];
        }
        __syncthreads();
        #pragma unroll 4
        for (int kk=0;kk<64;kk++){
            float pv[4], vv[4];
            #pragma unroll
            for (int i=0;i<4;i++) pv[i]=p_s[(ty*4+i)*65+kk];
            #pragma unroll
            for (int j=0;j<4;j++) vv[j]=kv_s[kk*65 + tx*4 + j];
            #pragma unroll
            for (int i=0;i<4;i++)
                #pragma unroll
                for (int j=0;j<4;j++) acc[i][j] += pv[i]*vv[j];
        }
        __syncthreads();
    }

    #pragma unroll
    for (int i=0;i<4;i++){
        int qg = q0 + ty*4 + i;
        float l = l_s[ty*4+i];
        float inv = (l > 0.f) ? 1.f/l : 0.f;
        float g = d_gate[qg*GDIM + h*3 + (MODE==0 ? 1 : 2)];
        #pragma unroll
        for (int j=0;j<4;j++)
            d_oacc[qg*DIMM + h*64 + tx*4 + j] += g * acc[i][j] * inv;
    }
}

// ---------------- launch ----------------
extern "C" void kernel_launch(void* const* d_in, const int* in_sizes, int n_in,
                              void* d_out, int out_size)
{
    (void)in_sizes; (void)n_in; (void)out_size;
    const float* x      = (const float*)d_in[0];
    const float* wq     = (const float*)d_in[1];
    const float* wk     = (const float*)d_in[2];
    const float* wv     = (const float*)d_in[3];
    const float* wo     = (const float*)d_in[4];
    const float* gw1    = (const float*)d_in[5];
    const float* gw2    = (const float*)d_in[6];
    const float* pe_k   = (const float*)d_in[7];
    const float* down_k = (const float*)d_in[8];
    const float* stop_k = (const float*)d_in[9];
    const float* pe_v   = (const float*)d_in[10];
    const float* down_v = (const float*)d_in[11];
    const float* stop_v = (const float*)d_in[12];

    float *q_p, *k_p, *v_p, *g1_p, *gate_p, *kc_p, *vc_p, *oacc_p;
    cudaGetSymbolAddress((void**)&q_p,    d_q);
    cudaGetSymbolAddress((void**)&k_p,    d_k);
    cudaGetSymbolAddress((void**)&v_p,    d_v);
    cudaGetSymbolAddress((void**)&g1_p,   d_g1);
    cudaGetSymbolAddress((void**)&gate_p, d_gate);
    cudaGetSymbolAddress((void**)&kc_p,   d_kc);
    cudaGetSymbolAddress((void**)&vc_p,   d_vc);
    cudaGetSymbolAddress((void**)&oacc_p, d_oacc);

    const float scale = 0.125f;  // 1/sqrt(64)

    // projections + gate
    gemm128<<<dim3(8,16),256>>>(x, wq, q_p, S, DIMM, DIMM, EPI_HEAD);
    gemm128<<<dim3(8,16),256>>>(x, wk, k_p, S, DIMM, DIMM, EPI_HEAD);
    gemm128<<<dim3(8,16),256>>>(x, wv, v_p, S, DIMM, DIMM, EPI_HEAD);
    gemm128<<<dim3(4,16),256>>>(x, gw1, g1_p, S, 512, DIMM, EPI_SILU);
    gemm128<<<dim3(1,16),256>>>(g1_p, gw2, gate_p, S, GDIM, 512, EPI_SIGMOID);

    // compression
    compress_kernel<<<dim3(128,16),64>>>(k_p, pe_k, down_k, stop_k, kc_p);
    compress_kernel<<<dim3(128,16),64>>>(v_p, pe_v, down_v, stop_v, vc_p);

    // compressed branch + selection masks
    const int CSM = (8192+8192+64+128+32+4)*4;
    cudaFuncSetAttribute(cmp_attn, cudaFuncAttributeMaxDynamicSharedMemorySize, CSM);
    cmp_attn<<<dim3(S/8,16),128,CSM>>>(scale);

    // sparse branches
    const int FSM = (3*64*65 + 64 + 64)*4 + 65*4;
    cudaFuncSetAttribute(attn_flash<0>, cudaFuncAttributeMaxDynamicSharedMemorySize, FSM);
    cudaFuncSetAttribute(attn_flash<1>, cudaFuncAttributeMaxDynamicSharedMemorySize, FSM);
    attn_flash<0><<<dim3(S/64,16),256,FSM>>>(scale);
    attn_flash<1><<<dim3(S/64,16),256,FSM>>>(scale);

    // output projection
    gemm128<<<dim3(8,16),256>>>(oacc_p, wo, (float*)d_out, S, DIMM, DIMM, EPI_NONE);
}

// round 2
// speedup vs baseline: 1.1707x; 1.1707x over previous
#include <cuda_runtime.h>
#include <math.h>

#define H    16
#define S    2048
#define D    64
#define DIMM 1024
#define SCMP 128
#define GDIM 48

#define BM 128
#define BN 128
#define BK 16

// ---------------- scratch ----------------
__device__ float d_q[H*S*D];
__device__ float d_k[H*S*D];
__device__ float d_v[H*S*D];
__device__ float d_g1[S*512];
__device__ float d_gate[S*GDIM];
__device__ float d_kc[H*SCMP*D];
__device__ float d_vc[H*SCMP*D];
__device__ float d_o1[S*DIMM];
__device__ float d_o2[S*DIMM];
__device__ float d_o3[S*DIMM];
__device__ unsigned d_bm[H*S];

enum { EPI_NONE=0, EPI_SILU=1, EPI_SIGMOID=2, EPI_HEAD=3 };

// ---------------- double-buffered fp32 GEMM ----------------
// C = epi(A @ B), A:[M,K] (optionally A+Ab+Ac summed on load), B:[K,N].
// blockIdx.z selects (B,C) pair for the fused QKV launch.
// Requires: M multiple of 128, K multiple of 16, N%4==0.
__global__ __launch_bounds__(256,2)
void gemm_big(const float* __restrict__ A,
              const float* __restrict__ Ab,
              const float* __restrict__ Ac,
              const float* __restrict__ B0,
              const float* __restrict__ B1,
              const float* __restrict__ B2,
              float* __restrict__ C0,
              float* __restrict__ C1,
              float* __restrict__ C2,
              int M, int N, int K, int epi)
{
    __shared__ __align__(16) float As[2][BK][BM];
    __shared__ __align__(16) float Bs[2][BK][BN];
    const int tid = threadIdx.x;
    const int tx = tid & 15, ty = tid >> 4;
    const int m0 = blockIdx.y * BM, n0 = blockIdx.x * BN;
    const float* B = blockIdx.z==0 ? B0 : (blockIdx.z==1 ? B1 : B2);
    float* C = blockIdx.z==0 ? C0 : (blockIdx.z==1 ? C1 : C2);

    const int arow = tid & 127;
    const int akq  = tid >> 7;          // 0..1 (handles kq and kq+2)
    const int bkk  = tid >> 5;          // 0..7 (handles kk and kk+8)
    const int bn   = (tid & 31) * 4;

    const long abase = (long)(m0 + arow) * K;
    const bool bok = (n0 + bn) < N;

    float4 ra[2], rb[2];
    float acc[8][8];
    #pragma unroll
    for (int i=0;i<8;i++)
        #pragma unroll
        for (int j=0;j<8;j++) acc[i][j]=0.f;

    const int nT = K / BK;

    // prologue: tile 0
    #pragma unroll
    for (int i=0;i<2;i++){
        long off = abase + (akq + i*2)*4;
        float4 v = *(const float4*)(A + off);
        if (Ab){
            float4 w = *(const float4*)(Ab + off);
            float4 u = *(const float4*)(Ac + off);
            v.x+=w.x+u.x; v.y+=w.y+u.y; v.z+=w.z+u.z; v.w+=w.w+u.w;
        }
        ra[i]=v;
        rb[i]= bok ? *(const float4*)(B + (long)(bkk + i*8)*N + n0 + bn)
                   : make_float4(0.f,0.f,0.f,0.f);
    }
    #pragma unroll
    for (int i=0;i<2;i++){
        int kq=(akq+i*2)*4;
        As[0][kq+0][arow]=ra[i].x; As[0][kq+1][arow]=ra[i].y;
        As[0][kq+2][arow]=ra[i].z; As[0][kq+3][arow]=ra[i].w;
        *(float4*)&Bs[0][bkk+i*8][bn] = rb[i];
    }
    __syncthreads();

    int buf=0;
    for (int t=0;t<nT;t++){
        if (t+1<nT){
            int k0=(t+1)*BK;
            #pragma unroll
            for (int i=0;i<2;i++){
                long off = abase + k0 + (akq + i*2)*4;
                float4 v = *(const float4*)(A + off);
                if (Ab){
                    float4 w = *(const float4*)(Ab + off);
                    float4 u = *(const float4*)(Ac + off);
                    v.x+=w.x+u.x; v.y+=w.y+u.y; v.z+=w.z+u.z; v.w+=w.w+u.w;
                }
                ra[i]=v;
                rb[i]= bok ? *(const float4*)(B + (long)(k0 + bkk + i*8)*N + n0 + bn)
                           : make_float4(0.f,0.f,0.f,0.f);
            }
        }
        #pragma unroll
        for (int kk=0;kk<BK;kk++){
            float4 a0=*(const float4*)&As[buf][kk][ty*8];
            float4 a1=*(const float4*)&As[buf][kk][ty*8+4];
            float4 b0=*(const float4*)&Bs[buf][kk][tx*8];
            float4 b1=*(const float4*)&Bs[buf][kk][tx*8+4];
            float av[8]={a0.x,a0.y,a0.z,a0.w,a1.x,a1.y,a1.z,a1.w};
            float bv[8]={b0.x,b0.y,b0.z,b0.w,b1.x,b1.y,b1.z,b1.w};
            #pragma unroll
            for (int i=0;i<8;i++)
                #pragma unroll
                for (int j=0;j<8;j++) acc[i][j] += av[i]*bv[j];
        }
        if (t+1<nT){
            int nb=buf^1;
            #pragma unroll
            for (int i=0;i<2;i++){
                int kq=(akq+i*2)*4;
                As[nb][kq+0][arow]=ra[i].x; As[nb][kq+1][arow]=ra[i].y;
                As[nb][kq+2][arow]=ra[i].z; As[nb][kq+3][arow]=ra[i].w;
                *(float4*)&Bs[nb][bkk+i*8][bn] = rb[i];
            }
        }
        __syncthreads();
        buf^=1;
    }

    #pragma unroll
    for (int i=0;i<8;i++){
        int gm = m0 + ty*8 + i;
        #pragma unroll
        for (int j=0;j<8;j++){
            int gn = n0 + tx*8 + j;
            if (gn >= N) continue;
            float vv = acc[i][j];
            if (epi==EPI_SILU)         vv = vv/(1.f+__expf(-vv));
            else if (epi==EPI_SIGMOID) vv = 1.f/(1.f+__expf(-vv));
            if (epi==EPI_HEAD) C[((gn>>6)*S + gm)*D + (gn&63)] = vv;
            else               C[(long)gm*N + gn] = vv;
        }
    }
}

// ---------------- compression Phi: [H,S,D] -> [H,SCMP,D] ----------------
__global__ void compress_kernel(const float* __restrict__ src, const float* __restrict__ pe,
                                const float* __restrict__ down, const float* __restrict__ stop,
                                float* __restrict__ dst)
{
    __shared__ float bufA[32*64];
    __shared__ float bufB[16*64];
    int w = blockIdx.x, h = blockIdx.y, d = threadIdx.x;
    if (w == 0){ dst[(h*SCMP + 0)*D + d] = 0.f; return; }
    int s0 = (w-1)*16;
    #pragma unroll
    for (int i=0;i<32;i++)
        bufA[i*64+d] = src[(h*S + s0+i)*D + d] + pe[i*64+d];
    __syncthreads();

    float* cur = bufA; float* nxt = bufB;
    int L = 32;
    for (int lev=0; lev<5; lev++){
        int P = L >> 1;
        float accs[16];
        #pragma unroll
        for (int p=0;p<16;p++) accs[p]=0.f;
        const float* W = down + lev*(128*64);
        for (int j=0;j<128;j++){
            float wv = W[j*64 + d];
            int base = (j>>6)*64 + (j&63);
            #pragma unroll
            for (int p=0;p<16;p++)
                if (p < P) accs[p] += cur[p*128 + base]*wv;
        }
        for (int p=0;p<P;p++){
            float xx = accs[p];
            nxt[p*64+d] = xx / (1.f + __expf(-xx));
        }
        __syncthreads();
        float* t = cur; cur = nxt; nxt = t;
        L = P;
    }
    float a = 0.f;
    #pragma unroll
    for (int j=0;j<64;j++) a += cur[j]*stop[j*64+d];
    dst[(h*SCMP + w)*D + d] = a;
}

// ---------------- compressed branch + conv + top-k selection ----------------
__global__ void cmp_attn(float scale)
{
    extern __shared__ float csm[];
    float* kc_s = csm;             // 8192
    float* vc_s = kc_s + 8192;     // 8192
    float* q_s  = vc_s + 8192;     // 64
    float* p_sm = q_s + 64;        // 128
    float* ps   = p_sm + 128;      // 32
    float* ps2  = ps + 32;         // 64
    float* red  = ps2 + 64;        // 4

    int h = blockIdx.y;
    int tid = threadIdx.x;
    int lane = tid & 31, wid = tid >> 5;

    for (int i=tid;i<8192;i+=128){ kc_s[i]=d_kc[h*8192+i]; vc_s[i]=d_vc[h*8192+i]; }

    for (int qi=0;qi<8;qi++){
        int q = blockIdx.x*8 + qi;
        __syncthreads();
        if (tid < 64) q_s[tid] = d_q[(h*S + q)*D + tid];
        __syncthreads();

        int r = q >> 4;
        float sc = -INFINITY;
        {
            bool ok = (tid <= r-1) || (tid==0 && r<32);
            if (ok){
                float a=0.f;
                #pragma unroll
                for (int dd=0;dd<64;dd++) a += q_s[dd]*kc_s[tid*64+dd];
                sc = a*scale;
            }
        }
        float v = sc;
        #pragma unroll
        for (int off=16;off;off>>=1) v = fmaxf(v, __shfl_xor_sync(0xffffffffu,v,off));
        if (lane==0) red[wid]=v;
        __syncthreads();
        float m = fmaxf(fmaxf(red[0],red[1]),fmaxf(red[2],red[3]));
        float p = __expf(sc - m);
        p_sm[tid] = p;
        __syncthreads();
        float sv = p;
        #pragma unroll
        for (int off=16;off;off>>=1) sv += __shfl_xor_sync(0xffffffffu,sv,off);
        if (lane==0) red[wid]=sv;
        __syncthreads();
        float l = red[0]+red[1]+red[2]+red[3];

        // conv1d [1,2,2,2,1] stride 4 pad 1, stable-rank top-16 (warp 3)
        if (wid == 3){
            int n = lane;
            float a = 2.f*(p_sm[4*n] + p_sm[4*n+1] + p_sm[4*n+2]) + p_sm[4*n+3];
            if (4*n-1 >= 0) a += p_sm[4*n-1];
            ps[n] = a;
            __syncwarp();
            float mv = ps[n];
            int cnt = 0;
            #pragma unroll
            for (int i2=0;i2<32;i2++){
                float vi = ps[i2];
                cnt += (vi > mv) || (vi == mv && i2 < n);
            }
            bool sel = (cnt < 16) && (n < (q >> 6));
            unsigned msk = __ballot_sync(0xffffffffu, sel);
            if (lane==0) d_bm[h*S + q] = msk;
        }
        // P @ V, split across both halves of the block
        float a;
        if (tid < 64){
            a = 0.f;
            for (int j=0;j<64;j++) a += p_sm[j]*vc_s[j*64+tid];
        } else {
            float b = 0.f;
            int dd = tid - 64;
            for (int j=64;j<128;j++) b += p_sm[j]*vc_s[j*64+dd];
            ps2[dd] = b;
            a = 0.f;
        }
        __syncthreads();
        if (tid < 64){
            float g0 = d_gate[q*GDIM + h*3 + 0];
            d_o1[q*DIMM + h*64 + tid] = g0 * ((a + ps2[tid]) / l);
        }
    }
}

// ---------------- flash-style sparse attention ----------------
// MODE 0 = selection (writes d_o2), MODE 1 = sliding window (writes d_o3)
template<int MODE>
__global__ void attn_flash(float scale)
{
    extern __shared__ float fsm[];
    float* q_s  = fsm;
    float* kv_s = q_s  + 64*65;
    float* p_s  = kv_s + 64*65;
    float* m_s  = p_s  + 64*65;
    float* l_s  = m_s + 64;
    unsigned* msk_s = (unsigned*)(l_s + 64);
    unsigned* u_s   = msk_s + 64;

    int tq = blockIdx.x, h = blockIdx.y;
    int q0 = tq*64;
    int tid = threadIdx.x;
    int tx = tid & 15, ty = tid >> 4;

    #pragma unroll
    for (int r2=0;r2<16;r2++){
        int li = tid + r2*256;
        int row = li>>6, col = li&63;
        q_s[row*65+col] = d_q[(h*S + q0+row)*D + col];
    }
    if (tid < 64){
        m_s[tid] = -INFINITY; l_s[tid] = 0.f;
        if (MODE==0) msk_s[tid] = d_bm[h*S + q0 + tid];
    }
    __syncthreads();

    unsigned uni = 0xFFFFFFFFu;
    if (MODE==0){
        if (tid==0){
            unsigned u=0;
            for (int i=0;i<64;i++) u |= msk_s[i];
            u_s[0]=u;
        }
        __syncthreads();
        uni = u_s[0];
    }

    int nlo, nhi;
    if (MODE==0){ nlo=0; nhi=(uni==0u)?0:tq; }
    else { nlo = tq-8; if (nlo<0) nlo=0; nhi = tq+1; }

    float acc[4][4];
    #pragma unroll
    for (int i=0;i<4;i++)
        #pragma unroll
        for (int j=0;j<4;j++) acc[i][j]=0.f;

    for (int n=nlo;n<nhi;n++){
        if (MODE==0 && !((uni>>n)&1u)) continue;

        #pragma unroll
        for (int r2=0;r2<16;r2++){
            int li = tid + r2*256;
            int row = li>>6, col = li&63;
            kv_s[row*65+col] = d_k[(h*S + n*64+row)*D + col];
        }
        __syncthreads();

        float s[4][4];
        #pragma unroll
        for (int i=0;i<4;i++)
            #pragma unroll
            for (int j=0;j<4;j++) s[i][j]=0.f;
        #pragma unroll 8
        for (int dd=0;dd<64;dd++){
            float qv[4], kv[4];
            #pragma unroll
            for (int i=0;i<4;i++) qv[i]=q_s[(ty*4+i)*65 + dd];
            #pragma unroll
            for (int j=0;j<4;j++) kv[j]=kv_s[(tx*4+j)*65 + dd];
            #pragma unroll
            for (int i=0;i<4;i++)
                #pragma unroll
                for (int j=0;j<4;j++) s[i][j] += qv[i]*kv[j];
        }

        float amn[4], anl[4];
        #pragma unroll
        for (int i=0;i<4;i++){
            int qi = ty*4+i;
            int qg = q0 + qi;
            unsigned mbits = (MODE==0) ? msk_s[qi] : 0u;
            float rm = -INFINITY;
            #pragma unroll
            for (int j=0;j<4;j++){
                bool ok;
                if (MODE==0) ok = (mbits>>n)&1u;
                else { int t = n*64 + tx*4 + j; ok = (t <= qg) && (qg - t <= 512); }
                float val = ok ? s[i][j]*scale : -INFINITY;
                s[i][j]=val;
                rm = fmaxf(rm, val);
            }
            #pragma unroll
            for (int off=8;off;off>>=1) rm = fmaxf(rm, __shfl_xor_sync(0xffffffffu, rm, off));
            float mo = m_s[qi];
            float mn = fmaxf(mo, rm);
            float alpha = 1.f, ts = 0.f;
            if (mn == -INFINITY){
                #pragma unroll
                for (int j=0;j<4;j++) s[i][j]=0.f;
            } else {
                alpha = __expf(mo - mn);
                #pragma unroll
                for (int j=0;j<4;j++){ float pp = __expf(s[i][j]-mn); s[i][j]=pp; ts += pp; }
            }
            #pragma unroll
            for (int off=8;off;off>>=1) ts += __shfl_xor_sync(0xffffffffu, ts, off);
            #pragma unroll
            for (int j=0;j<4;j++) p_s[qi*65 + tx*4 + j] = s[i][j];
            #pragma unroll
            for (int j=0;j<4;j++) acc[i][j] *= alpha;
            amn[i]=mn; anl[i]=l_s[qi]*alpha + ts;
        }
        __syncthreads();
        if (tx==0){
            #pragma unroll
            for (int i=0;i<4;i++){ m_s[ty*4+i]=amn[i]; l_s[ty*4+i]=anl[i]; }
        }
        #pragma unroll
        for (int r2=0;r2<16;r2++){
            int li = tid + r2*256;
            int row = li>>6, col = li&63;
            kv_s[row*65+col] = d_v[(h*S + n*64+row)*D + col];
        }
        __syncthreads();
        #pragma unroll 4
        for (int kk=0;kk<64;kk++){
            float pv[4], vv[4];
            #pragma unroll
            for (int i=0;i<4;i++) pv[i]=p_s[(ty*4+i)*65+kk];
            #pragma unroll
            for (int j=0;j<4;j++) vv[j]=kv_s[kk*65 + tx*4 + j];
            #pragma unroll
            for (int i=0;i<4;i++)
                #pragma unroll
                for (int j=0;j<4;j++) acc[i][j] += pv[i]*vv[j];
        }
        __syncthreads();
    }

    float* outp = (MODE==0) ? d_o2 : d_o3;
    #pragma unroll
    for (int i=0;i<4;i++){
        int qg = q0 + ty*4 + i;
        float l = l_s[ty*4+i];
        float inv = (l > 0.f) ? 1.f/l : 0.f;
        float g = d_gate[qg*GDIM + h*3 + (MODE==0 ? 1 : 2)];
        #pragma unroll
        for (int j=0;j<4;j++)
            outp[qg*DIMM + h*64 + tx*4 + j] = g * acc[i][j] * inv;
    }
}

// ---------------- launch ----------------
static cudaStream_t sA = nullptr, sB = nullptr;
static cudaEvent_t e0, e_qkv, e_gate, e_cv, e_cmp, e_f0, e_f1;

extern "C" void kernel_launch(void* const* d_in, const int* in_sizes, int n_in,
                              void* d_out, int out_size)
{
    (void)in_sizes; (void)n_in; (void)out_size;
    const float* x      = (const float*)d_in[0];
    const float* wq     = (const float*)d_in[1];
    const float* wk     = (const float*)d_in[2];
    const float* wv     = (const float*)d_in[3];
    const float* wo     = (const float*)d_in[4];
    const float* gw1    = (const float*)d_in[5];
    const float* gw2    = (const float*)d_in[6];
    const float* pe_k   = (const float*)d_in[7];
    const float* down_k = (const float*)d_in[8];
    const float* stop_k = (const float*)d_in[9];
    const float* pe_v   = (const float*)d_in[10];
    const float* down_v = (const float*)d_in[11];
    const float* stop_v = (const float*)d_in[12];

    if (!sA){
        cudaStreamCreateWithFlags(&sA, cudaStreamNonBlocking);
        cudaStreamCreateWithFlags(&sB, cudaStreamNonBlocking);
        cudaEventCreateWithFlags(&e0,     cudaEventDisableTiming);
        cudaEventCreateWithFlags(&e_qkv,  cudaEventDisableTiming);
        cudaEventCreateWithFlags(&e_gate, cudaEventDisableTiming);
        cudaEventCreateWithFlags(&e_cv,   cudaEventDisableTiming);
        cudaEventCreateWithFlags(&e_cmp,  cudaEventDisableTiming);
        cudaEventCreateWithFlags(&e_f0,   cudaEventDisableTiming);
        cudaEventCreateWithFlags(&e_f1,   cudaEventDisableTiming);
        const int CSM = (8192+8192+64+128+32+64+4)*4;
        cudaFuncSetAttribute(cmp_attn, cudaFuncAttributeMaxDynamicSharedMemorySize, CSM);
        const int FSM = (3*64*65 + 64 + 64)*4 + 65*4;
        cudaFuncSetAttribute(attn_flash<0>, cudaFuncAttributeMaxDynamicSharedMemorySize, FSM);
        cudaFuncSetAttribute(attn_flash<1>, cudaFuncAttributeMaxDynamicSharedMemorySize, FSM);
    }

    float *q_p, *k_p, *v_p, *g1_p, *gate_p, *kc_p, *vc_p, *o1_p, *o2_p, *o3_p;
    cudaGetSymbolAddress((void**)&q_p,    d_q);
    cudaGetSymbolAddress((void**)&k_p,    d_k);
    cudaGetSymbolAddress((void**)&v_p,    d_v);
    cudaGetSymbolAddress((void**)&g1_p,   d_g1);
    cudaGetSymbolAddress((void**)&gate_p, d_gate);
    cudaGetSymbolAddress((void**)&kc_p,   d_kc);
    cudaGetSymbolAddress((void**)&vc_p,   d_vc);
    cudaGetSymbolAddress((void**)&o1_p,   d_o1);
    cudaGetSymbolAddress((void**)&o2_p,   d_o2);
    cudaGetSymbolAddress((void**)&o3_p,   d_o3);

    const float scale = 0.125f;
    const int CSM = (8192+8192+64+128+32+64+4)*4;
    const int FSM = (3*64*65 + 64 + 64)*4 + 65*4;

    // fork
    cudaEventRecord(e0, 0);
    cudaStreamWaitEvent(sA, e0, 0);
    cudaStreamWaitEvent(sB, e0, 0);

    // stream0: fused QKV projection
    gemm_big<<<dim3(8,16,3),256>>>(x, nullptr, nullptr, wq, wk, wv,
                                   q_p, k_p, v_p, S, 1024, DIMM, EPI_HEAD);
    cudaEventRecord(e_qkv, 0);

    // sA: gate chain
    gemm_big<<<dim3(4,16,1),256,0,sA>>>(x, nullptr, nullptr, gw1, gw1, gw1,
                                        g1_p, g1_p, g1_p, S, 512, DIMM, EPI_SILU);
    gemm_big<<<dim3(1,16,1),256,0,sA>>>(g1_p, nullptr, nullptr, gw2, gw2, gw2,
                                        gate_p, gate_p, gate_p, S, GDIM, 512, EPI_SIGMOID);
    cudaEventRecord(e_gate, sA);

    // sB: compress V (after QKV)
    cudaStreamWaitEvent(sB, e_qkv, 0);
    compress_kernel<<<dim3(128,16),64,0,sB>>>(v_p, pe_v, down_v, stop_v, vc_p);
    cudaEventRecord(e_cv, sB);

    // stream0: compress K, then compressed-branch attention (+ selection masks)
    compress_kernel<<<dim3(128,16),64>>>(k_p, pe_k, down_k, stop_k, kc_p);
    cudaStreamWaitEvent(0, e_gate, 0);
    cudaStreamWaitEvent(0, e_cv, 0);
    cmp_attn<<<dim3(S/8,16),128,CSM>>>(scale);
    cudaEventRecord(e_cmp, 0);

    // sA: sliding-window branch (needs q,k,v,gate)
    cudaStreamWaitEvent(sA, e_qkv, 0);
    attn_flash<1><<<dim3(S/64,16),256,FSM,sA>>>(scale);
    cudaEventRecord(e_f1, sA);

    // sB: selection branch (needs bitmasks from cmp_attn, gate)
    cudaStreamWaitEvent(sB, e_cmp, 0);
    cudaStreamWaitEvent(sB, e_gate, 0);
    attn_flash<0><<<dim3(S/64,16),256,FSM,sB>>>(scale);
    cudaEventRecord(e_f0, sB);

    // join + output projection (A = o1+o2+o3 summed on load)
    cudaStreamWaitEvent(0, e_f1, 0);
    cudaStreamWaitEvent(0, e_f0, 0);
    gemm_big<<<dim3(8,16,1),256>>>(o1_p, o2_p, o3_p, wo, wo, wo,
                                   (float*)d_out, (float*)d_out, (float*)d_out,
                                   S, DIMM, DIMM, EPI_NONE);
}

// round 3
// speedup vs baseline: 1.4596x; 1.2467x over previous
#include <cuda_runtime.h>
#include <math.h>

#define H    16
#define S    2048
#define D    64
#define DIMM 1024
#define SCMP 128
#define GDIM 48

#define BM 128
#define BN 128
#define BK 16

// ---------------- scratch ----------------
__device__ float d_q[H*S*D];
__device__ float d_k[H*S*D];
__device__ float d_v[H*S*D];
__device__ float d_g1[S*512];
__device__ float d_gate[S*GDIM];
__device__ float d_kc[H*SCMP*D];
__device__ float d_vc[H*SCMP*D];
__device__ float d_o1[S*DIMM];
__device__ float d_o2[S*DIMM];
__device__ float d_o3[S*DIMM];
__device__ unsigned d_bm[H*S];

enum { EPI_NONE=0, EPI_SILU=1, EPI_SIGMOID=2, EPI_HEAD=3 };

// ---------------- double-buffered fp32 GEMM ----------------
__global__ __launch_bounds__(256,2)
void gemm_big(const float* __restrict__ A,
              const float* __restrict__ Ab,
              const float* __restrict__ Ac,
              const float* __restrict__ B0,
              const float* __restrict__ B1,
              const float* __restrict__ B2,
              float* __restrict__ C0,
              float* __restrict__ C1,
              float* __restrict__ C2,
              int M, int N, int K, int epi)
{
    __shared__ __align__(16) float As[2][BK][BM];
    __shared__ __align__(16) float Bs[2][BK][BN];
    const int tid = threadIdx.x;
    const int tx = tid & 15, ty = tid >> 4;
    const int m0 = blockIdx.y * BM, n0 = blockIdx.x * BN;
    const float* B = blockIdx.z==0 ? B0 : (blockIdx.z==1 ? B1 : B2);
    float* C = blockIdx.z==0 ? C0 : (blockIdx.z==1 ? C1 : C2);

    const int arow = tid & 127;
    const int akq  = tid >> 7;
    const int bkk  = tid >> 5;
    const int bn   = (tid & 31) * 4;

    const long abase = (long)(m0 + arow) * K;
    const bool bok = (n0 + bn) < N;

    float4 ra[2], rb[2];
    float acc[8][8];
    #pragma unroll
    for (int i=0;i<8;i++)
        #pragma unroll
        for (int j=0;j<8;j++) acc[i][j]=0.f;

    const int nT = K / BK;

    #pragma unroll
    for (int i=0;i<2;i++){
        long off = abase + (akq + i*2)*4;
        float4 v = *(const float4*)(A + off);
        if (Ab){
            float4 w = *(const float4*)(Ab + off);
            float4 u = *(const float4*)(Ac + off);
            v.x+=w.x+u.x; v.y+=w.y+u.y; v.z+=w.z+u.z; v.w+=w.w+u.w;
        }
        ra[i]=v;
        rb[i]= bok ? *(const float4*)(B + (long)(bkk + i*8)*N + n0 + bn)
                   : make_float4(0.f,0.f,0.f,0.f);
    }
    #pragma unroll
    for (int i=0;i<2;i++){
        int kq=(akq+i*2)*4;
        As[0][kq+0][arow]=ra[i].x; As[0][kq+1][arow]=ra[i].y;
        As[0][kq+2][arow]=ra[i].z; As[0][kq+3][arow]=ra[i].w;
        *(float4*)&Bs[0][bkk+i*8][bn] = rb[i];
    }
    __syncthreads();

    int buf=0;
    for (int t=0;t<nT;t++){
        if (t+1<nT){
            int k0=(t+1)*BK;
            #pragma unroll
            for (int i=0;i<2;i++){
                long off = abase + k0 + (akq + i*2)*4;
                float4 v = *(const float4*)(A + off);
                if (Ab){
                    float4 w = *(const float4*)(Ab + off);
                    float4 u = *(const float4*)(Ac + off);
                    v.x+=w.x+u.x; v.y+=w.y+u.y; v.z+=w.z+u.z; v.w+=w.w+u.w;
                }
                ra[i]=v;
                rb[i]= bok ? *(const float4*)(B + (long)(k0 + bkk + i*8)*N + n0 + bn)
                           : make_float4(0.f,0.f,0.f,0.f);
            }
        }
        #pragma unroll
        for (int kk=0;kk<BK;kk++){
            float4 a0=*(const float4*)&As[buf][kk][ty*8];
            float4 a1=*(const float4*)&As[buf][kk][ty*8+4];
            float4 b0=*(const float4*)&Bs[buf][kk][tx*8];
            float4 b1=*(const float4*)&Bs[buf][kk][tx*8+4];
            float av[8]={a0.x,a0.y,a0.z,a0.w,a1.x,a1.y,a1.z,a1.w};
            float bv[8]={b0.x,b0.y,b0.z,b0.w,b1.x,b1.y,b1.z,b1.w};
            #pragma unroll
            for (int i=0;i<8;i++)
                #pragma unroll
                for (int j=0;j<8;j++) acc[i][j] += av[i]*bv[j];
        }
        if (t+1<nT){
            int nb=buf^1;
            #pragma unroll
            for (int i=0;i<2;i++){
                int kq=(akq+i*2)*4;
                As[nb][kq+0][arow]=ra[i].x; As[nb][kq+1][arow]=ra[i].y;
                As[nb][kq+2][arow]=ra[i].z; As[nb][kq+3][arow]=ra[i].w;
                *(float4*)&Bs[nb][bkk+i*8][bn] = rb[i];
            }
        }
        __syncthreads();
        buf^=1;
    }

    #pragma unroll
    for (int i=0;i<8;i++){
        int gm = m0 + ty*8 + i;
        #pragma unroll
        for (int j=0;j<8;j++){
            int gn = n0 + tx*8 + j;
            if (gn >= N) continue;
            float vv = acc[i][j];
            if (epi==EPI_SILU)         vv = vv/(1.f+__expf(-vv));
            else if (epi==EPI_SIGMOID) vv = 1.f/(1.f+__expf(-vv));
            if (epi==EPI_HEAD) C[((gn>>6)*S + gm)*D + (gn&63)] = vv;
            else               C[(long)gm*N + gn] = vv;
        }
    }
}

// ---------------- compression Phi (rewritten) ----------------
// One level: b[p][d] = silu(sum_j a[p][j] * W[j][d]), a rows contiguous [P][128].
template<int P>
__device__ __forceinline__ void phi_level(const float* __restrict__ a,
                                          float* __restrict__ b,
                                          const float* __restrict__ W, int d)
{
    float accs[P];
    #pragma unroll
    for (int p=0;p<P;p++) accs[p]=0.f;
    #pragma unroll 4
    for (int j=0;j<128;j+=4){
        float w0=W[(j+0)*64+d], w1=W[(j+1)*64+d];
        float w2=W[(j+2)*64+d], w3=W[(j+3)*64+d];
        #pragma unroll
        for (int p=0;p<P;p++){
            float4 c = *(const float4*)&a[p*128+j];
            accs[p] += c.x*w0;
            accs[p] += c.y*w1;
            accs[p] += c.z*w2;
            accs[p] += c.w*w3;
        }
    }
    #pragma unroll
    for (int p=0;p<P;p++){
        float xx = accs[p];
        b[p*64+d] = xx / (1.f + __expf(-xx));
    }
}

// grid (32, H, 2): 4 windows per 256-thread block; z=0 -> K, z=1 -> V.
__global__ __launch_bounds__(256)
void compress2(const float* __restrict__ ksrc, const float* __restrict__ vsrc,
               const float* __restrict__ pe_k, const float* __restrict__ down_k,
               const float* __restrict__ stop_k,
               const float* __restrict__ pe_v, const float* __restrict__ down_v,
               const float* __restrict__ stop_v,
               float* __restrict__ kc, float* __restrict__ vc)
{
    __shared__ __align__(16) float bufX[4*2048];
    __shared__ __align__(16) float bufY[4*1024];
    const int tid = threadIdx.x;
    const int d   = tid & 63;
    const int sub = tid >> 6;
    const int w   = blockIdx.x*4 + sub;     // 0..127
    const int h   = blockIdx.y;
    const int z   = blockIdx.z;
    const float* src  = z ? vsrc  : ksrc;
    const float* pe   = z ? pe_v  : pe_k;
    const float* down = z ? down_v: down_k;
    const float* stop = z ? stop_v: stop_k;
    float* dst        = z ? vc    : kc;

    float* X = bufX + sub*2048;
    float* Y = bufY + sub*1024;

    if (w > 0){
        int s0 = (w-1)*16;
        #pragma unroll
        for (int i=0;i<32;i++)
            X[i*64+d] = src[(h*S + s0+i)*D + d] + pe[i*64+d];
    }
    __syncthreads();

    phi_level<16>(X, Y, down,         d);  __syncthreads();
    phi_level<8> (Y, X, down + 8192,  d);  __syncthreads();
    phi_level<4> (X, Y, down + 16384, d);  __syncthreads();
    phi_level<2> (Y, X, down + 24576, d);  __syncthreads();
    phi_level<1> (X, Y, down + 32768, d);  __syncthreads();

    float a = 0.f;
    #pragma unroll
    for (int j=0;j<64;j+=4){
        float4 c = *(const float4*)&Y[j];
        a += c.x*stop[(j+0)*64+d];
        a += c.y*stop[(j+1)*64+d];
        a += c.z*stop[(j+2)*64+d];
        a += c.w*stop[(j+3)*64+d];
    }
    dst[(h*SCMP + w)*D + d] = (w > 0) ? a : 0.f;
}

// ---------------- compressed branch + conv + top-k selection ----------------
__global__ void cmp_attn(float scale)
{
    extern __shared__ float csm[];
    float* kc_s = csm;             // 8192
    float* vc_s = kc_s + 8192;     // 8192
    float* q_s  = vc_s + 8192;     // 64
    float* p_sm = q_s + 64;        // 128
    float* ps   = p_sm + 128;      // 32
    float* ps2  = ps + 32;         // 64
    float* red  = ps2 + 64;        // 4

    int h = blockIdx.y;
    int tid = threadIdx.x;
    int lane = tid & 31, wid = tid >> 5;

    for (int i=tid;i<8192;i+=128){ kc_s[i]=d_kc[h*8192+i]; vc_s[i]=d_vc[h*8192+i]; }

    for (int qi=0;qi<8;qi++){
        int q = blockIdx.x*8 + qi;
        __syncthreads();
        if (tid < 64) q_s[tid] = d_q[(h*S + q)*D + tid];
        __syncthreads();

        int r = q >> 4;
        float sc = -INFINITY;
        {
            bool ok = (tid <= r-1) || (tid==0 && r<32);
            if (ok){
                float a=0.f;
                #pragma unroll
                for (int dd=0;dd<64;dd++) a += q_s[dd]*kc_s[tid*64+dd];
                sc = a*scale;
            }
        }
        float v = sc;
        #pragma unroll
        for (int off=16;off;off>>=1) v = fmaxf(v, __shfl_xor_sync(0xffffffffu,v,off));
        if (lane==0) red[wid]=v;
        __syncthreads();
        float m = fmaxf(fmaxf(red[0],red[1]),fmaxf(red[2],red[3]));
        float p = __expf(sc - m);
        p_sm[tid] = p;
        __syncthreads();
        float sv = p;
        #pragma unroll
        for (int off=16;off;off>>=1) sv += __shfl_xor_sync(0xffffffffu,sv,off);
        if (lane==0) red[wid]=sv;
        __syncthreads();
        float l = red[0]+red[1]+red[2]+red[3];

        if (wid == 3){
            int n = lane;
            float a = 2.f*(p_sm[4*n] + p_sm[4*n+1] + p_sm[4*n+2]) + p_sm[4*n+3];
            if (4*n-1 >= 0) a += p_sm[4*n-1];
            ps[n] = a;
            __syncwarp();
            float mv = ps[n];
            int cnt = 0;
            #pragma unroll
            for (int i2=0;i2<32;i2++){
                float vi = ps[i2];
                cnt += (vi > mv) || (vi == mv && i2 < n);
            }
            bool sel = (cnt < 16) && (n < (q >> 6));
            unsigned msk = __ballot_sync(0xffffffffu, sel);
            if (lane==0) d_bm[h*S + q] = msk;
        }
        float a;
        if (tid < 64){
            a = 0.f;
            for (int j=0;j<64;j++) a += p_sm[j]*vc_s[j*64+tid];
        } else {
            float b = 0.f;
            int dd = tid - 64;
            for (int j=64;j<128;j++) b += p_sm[j]*vc_s[j*64+dd];
            ps2[dd] = b;
            a = 0.f;
        }
        __syncthreads();
        if (tid < 64){
            float g0 = d_gate[q*GDIM + h*3 + 0];
            d_o1[q*DIMM + h*64 + tid] = g0 * ((a + ps2[tid]) / l);
        }
    }
}

// ---------------- flash-style sparse attention ----------------
template<int MODE>
__global__ void attn_flash(float scale)
{
    extern __shared__ float fsm[];
    float* q_s  = fsm;
    float* kv_s = q_s  + 64*65;
    float* p_s  = kv_s + 64*65;
    float* m_s  = p_s  + 64*65;
    float* l_s  = m_s + 64;
    unsigned* msk_s = (unsigned*)(l_s + 64);
    unsigned* u_s   = msk_s + 64;

    int tq = blockIdx.x, h = blockIdx.y;
    int q0 = tq*64;
    int tid = threadIdx.x;
    int tx = tid & 15, ty = tid >> 4;

    #pragma unroll
    for (int r2=0;r2<16;r2++){
        int li = tid + r2*256;
        int row = li>>6, col = li&63;
        q_s[row*65+col] = d_q[(h*S + q0+row)*D + col];
    }
    if (tid < 64){
        m_s[tid] = -INFINITY; l_s[tid] = 0.f;
        if (MODE==0) msk_s[tid] = d_bm[h*S + q0 + tid];
    }
    __syncthreads();

    unsigned uni = 0xFFFFFFFFu;
    if (MODE==0){
        if (tid==0){
            unsigned u=0;
            for (int i=0;i<64;i++) u |= msk_s[i];
            u_s[0]=u;
        }
        __syncthreads();
        uni = u_s[0];
    }

    int nlo, nhi;
    if (MODE==0){ nlo=0; nhi=(uni==0u)?0:tq; }
    else { nlo = tq-8; if (nlo<0) nlo=0; nhi = tq+1; }

    float acc[4][4];
    #pragma unroll
    for (int i=0;i<4;i++)
        #pragma unroll
        for (int j=0;j<4;j++) acc[i][j]=0.f;

    for (int n=nlo;n<nhi;n++){
        if (MODE==0 && !((uni>>n)&1u)) continue;

        #pragma unroll
        for (int r2=0;r2<16;r2++){
            int li = tid + r2*256;
            int row = li>>6, col = li&63;
            kv_s[row*65+col] = d_k[(h*S + n*64+row)*D + col];
        }
        __syncthreads();

        float s[4][4];
        #pragma unroll
        for (int i=0;i<4;i++)
            #pragma unroll
            for (int j=0;j<4;j++) s[i][j]=0.f;
        #pragma unroll 8
        for (int dd=0;dd<64;dd++){
            float qv[4], kv[4];
            #pragma unroll
            for (int i=0;i<4;i++) qv[i]=q_s[(ty*4+i)*65 + dd];
            #pragma unroll
            for (int j=0;j<4;j++) kv[j]=kv_s[(tx*4+j)*65 + dd];
            #pragma unroll
            for (int i=0;i<4;i++)
                #pragma unroll
                for (int j=0;j<4;j++) s[i][j] += qv[i]*kv[j];
        }

        float amn[4], anl[4];
        #pragma unroll
        for (int i=0;i<4;i++){
            int qi = ty*4+i;
            int qg = q0 + qi;
            unsigned mbits = (MODE==0) ? msk_s[qi] : 0u;
            float rm = -INFINITY;
            #pragma unroll
            for (int j=0;j<4;j++){
                bool ok;
                if (MODE==0) ok = (mbits>>n)&1u;
                else { int t = n*64 + tx*4 + j; ok = (t <= qg) && (qg - t <= 512); }
                float val = ok ? s[i][j]*scale : -INFINITY;
                s[i][j]=val;
                rm = fmaxf(rm, val);
            }
            #pragma unroll
            for (int off=8;off;off>>=1) rm = fmaxf(rm, __shfl_xor_sync(0xffffffffu, rm, off));
            float mo = m_s[qi];
            float mn = fmaxf(mo, rm);
            float alpha = 1.f, ts = 0.f;
            if (mn == -INFINITY){
                #pragma unroll
                for (int j=0;j<4;j++) s[i][j]=0.f;
            } else {
                alpha = __expf(mo - mn);
                #pragma unroll
                for (int j=0;j<4;j++){ float pp = __expf(s[i][j]-mn); s[i][j]=pp; ts += pp; }
            }
            #pragma unroll
            for (int off=8;off;off>>=1) ts += __shfl_xor_sync(0xffffffffu, ts, off);
            #pragma unroll
            for (int j=0;j<4;j++) p_s[qi*65 + tx*4 + j] = s[i][j];
            #pragma unroll
            for (int j=0;j<4;j++) acc[i][j] *= alpha;
            amn[i]=mn; anl[i]=l_s[qi]*alpha + ts;
        }
        __syncthreads();
        if (tx==0){
            #pragma unroll
            for (int i=0;i<4;i++){ m_s[ty*4+i]=amn[i]; l_s[ty*4+i]=anl[i]; }
        }
        #pragma unroll
        for (int r2=0;r2<16;r2++){
            int li = tid + r2*256;
            int row = li>>6, col = li&63;
            kv_s[row*65+col] = d_v[(h*S + n*64+row)*D + col];
        }
        __syncthreads();
        #pragma unroll 4
        for (int kk=0;kk<64;kk++){
            float pv[4], vv[4];
            #pragma unroll
            for (int i=0;i<4;i++) pv[i]=p_s[(ty*4+i)*65+kk];
            #pragma unroll
            for (int j=0;j<4;j++) vv[j]=kv_s[kk*65 + tx*4 + j];
            #pragma unroll
            for (int i=0;i<4;i++)
                #pragma unroll
                for (int j=0;j<4;j++) acc[i][j] += pv[i]*vv[j];
        }
        __syncthreads();
    }

    float* outp = (MODE==0) ? d_o2 : d_o3;
    #pragma unroll
    for (int i=0;i<4;i++){
        int qg = q0 + ty*4 + i;
        float l = l_s[ty*4+i];
        float inv = (l > 0.f) ? 1.f/l : 0.f;
        float g = d_gate[qg*GDIM + h*3 + (MODE==0 ? 1 : 2)];
        #pragma unroll
        for (int j=0;j<4;j++)
            outp[qg*DIMM + h*64 + tx*4 + j] = g * acc[i][j] * inv;
    }
}

// ---------------- launch ----------------
static cudaStream_t sA = nullptr, sB = nullptr;
static cudaEvent_t e0, e_qkv, e_gate, e_cmp, e_f0, e_f1;

extern "C" void kernel_launch(void* const* d_in, const int* in_sizes, int n_in,
                              void* d_out, int out_size)
{
    (void)in_sizes; (void)n_in; (void)out_size;
    const float* x      = (const float*)d_in[0];
    const float* wq     = (const float*)d_in[1];
    const float* wk     = (const float*)d_in[2];
    const float* wv     = (const float*)d_in[3];
    const float* wo     = (const float*)d_in[4];
    const float* gw1    = (const float*)d_in[5];
    const float* gw2    = (const float*)d_in[6];
    const float* pe_k   = (const float*)d_in[7];
    const float* down_k = (const float*)d_in[8];
    const float* stop_k = (const float*)d_in[9];
    const float* pe_v   = (const float*)d_in[10];
    const float* down_v = (const float*)d_in[11];
    const float* stop_v = (const float*)d_in[12];

    if (!sA){
        cudaStreamCreateWithFlags(&sA, cudaStreamNonBlocking);
        cudaStreamCreateWithFlags(&sB, cudaStreamNonBlocking);
        cudaEventCreateWithFlags(&e0,     cudaEventDisableTiming);
        cudaEventCreateWithFlags(&e_qkv,  cudaEventDisableTiming);
        cudaEventCreateWithFlags(&e_gate, cudaEventDisableTiming);
        cudaEventCreateWithFlags(&e_cmp,  cudaEventDisableTiming);
        cudaEventCreateWithFlags(&e_f0,   cudaEventDisableTiming);
        cudaEventCreateWithFlags(&e_f1,   cudaEventDisableTiming);
        const int CSM = (8192+8192+64+128+32+64+4)*4;
        cudaFuncSetAttribute(cmp_attn, cudaFuncAttributeMaxDynamicSharedMemorySize, CSM);
        const int FSM = (3*64*65 + 64 + 64)*4 + 65*4;
        cudaFuncSetAttribute(attn_flash<0>, cudaFuncAttributeMaxDynamicSharedMemorySize, FSM);
        cudaFuncSetAttribute(attn_flash<1>, cudaFuncAttributeMaxDynamicSharedMemorySize, FSM);
    }

    float *q_p, *k_p, *v_p, *g1_p, *gate_p, *kc_p, *vc_p, *o1_p, *o2_p, *o3_p;
    cudaGetSymbolAddress((void**)&q_p,    d_q);
    cudaGetSymbolAddress((void**)&k_p,    d_k);
    cudaGetSymbolAddress((void**)&v_p,    d_v);
    cudaGetSymbolAddress((void**)&g1_p,   d_g1);
    cudaGetSymbolAddress((void**)&gate_p, d_gate);
    cudaGetSymbolAddress((void**)&kc_p,   d_kc);
    cudaGetSymbolAddress((void**)&vc_p,   d_vc);
    cudaGetSymbolAddress((void**)&o1_p,   d_o1);
    cudaGetSymbolAddress((void**)&o2_p,   d_o2);
    cudaGetSymbolAddress((void**)&o3_p,   d_o3);

    const float scale = 0.125f;
    const int CSM = (8192+8192+64+128+32+64+4)*4;
    const int FSM = (3*64*65 + 64 + 64)*4 + 65*4;

    cudaEventRecord(e0, 0);
    cudaStreamWaitEvent(sA, e0, 0);

    // stream0: fused QKV projection
    gemm_big<<<dim3(8,16,3),256>>>(x, nullptr, nullptr, wq, wk, wv,
                                   q_p, k_p, v_p, S, 1024, DIMM, EPI_HEAD);
    cudaEventRecord(e_qkv, 0);

    // sA: gate chain
    gemm_big<<<dim3(4,16,1),256,0,sA>>>(x, nullptr, nullptr, gw1, gw1, gw1,
                                        g1_p, g1_p, g1_p, S, 512, DIMM, EPI_SILU);
    gemm_big<<<dim3(1,16,1),256,0,sA>>>(g1_p, nullptr, nullptr, gw2, gw2, gw2,
                                        gate_p, gate_p, gate_p, S, GDIM, 512, EPI_SIGMOID);
    cudaEventRecord(e_gate, sA);

    // stream0: fused K+V compression, then compressed branch (+ masks)
    compress2<<<dim3(32,16,2),256>>>(k_p, v_p, pe_k, down_k, stop_k,
                                     pe_v, down_v, stop_v, kc_p, vc_p);
    cudaStreamWaitEvent(0, e_gate, 0);
    cmp_attn<<<dim3(S/8,16),128,CSM>>>(scale);
    cudaEventRecord(e_cmp, 0);

    // sA: sliding-window branch
    cudaStreamWaitEvent(sA, e_qkv, 0);
    attn_flash<1><<<dim3(S/64,16),256,FSM,sA>>>(scale);
    cudaEventRecord(e_f1, sA);

    // sB: selection branch (needs masks + gate)
    cudaStreamWaitEvent(sB, e_cmp, 0);
    cudaStreamWaitEvent(sB, e_gate, 0);
    attn_flash<0><<<dim3(S/64,16),256,FSM,sB>>>(scale);
    cudaEventRecord(e_f0, sB);

    // join + output projection
    cudaStreamWaitEvent(0, e_f1, 0);
    cudaStreamWaitEvent(0, e_f0, 0);
    gemm_big<<<dim3(8,16,1),256>>>(o1_p, o2_p, o3_p, wo, wo, wo,
                                   (float*)d_out, (float*)d_out, (float*)d_out,
                                   S, DIMM, DIMM, EPI_NONE);
}

// round 4
// speedup vs baseline: 1.4682x; 1.0060x over previous
#include <cuda_runtime.h>
#include <math.h>

#define H    16
#define S    2048
#define D    64
#define DIMM 1024
#define SCMP 128
#define GDIM 48

#define BM 128
#define BN 128
#define BK 16

// ---------------- scratch ----------------
__device__ float d_q[H*S*D];
__device__ float d_k[H*S*D];
__device__ float d_v[H*S*D];
__device__ float d_g1[S*512];
__device__ float d_gate[S*GDIM];
__device__ float d_kc[H*SCMP*D];
__device__ float d_vc[H*SCMP*D];
__device__ float d_o1[S*DIMM];
__device__ float d_o2[S*DIMM];
__device__ float d_o3[S*DIMM];
__device__ unsigned d_bm[H*S];

enum { EPI_NONE=0, EPI_SILU=1, EPI_SIGMOID=2, EPI_HEAD=3 };

// ---------------- double-buffered fp32 GEMM ----------------
__global__ __launch_bounds__(256,2)
void gemm_big(const float* __restrict__ A,
              const float* __restrict__ Ab,
              const float* __restrict__ Ac,
              const float* __restrict__ B0,
              const float* __restrict__ B1,
              const float* __restrict__ B2,
              float* __restrict__ C0,
              float* __restrict__ C1,
              float* __restrict__ C2,
              int M, int N, int K, int epi)
{
    __shared__ __align__(16) float As[2][BK][BM];
    __shared__ __align__(16) float Bs[2][BK][BN];
    const int tid = threadIdx.x;
    const int tx = tid & 15, ty = tid >> 4;
    const int m0 = blockIdx.y * BM, n0 = blockIdx.x * BN;
    const float* B = blockIdx.z==0 ? B0 : (blockIdx.z==1 ? B1 : B2);
    float* C = blockIdx.z==0 ? C0 : (blockIdx.z==1 ? C1 : C2);

    const int arow = tid & 127;
    const int akq  = tid >> 7;
    const int bkk  = tid >> 5;
    const int bn   = (tid & 31) * 4;

    const long abase = (long)(m0 + arow) * K;
    const bool bok = (n0 + bn) < N;

    float4 ra[2], rb[2];
    float acc[8][8];
    #pragma unroll
    for (int i=0;i<8;i++)
        #pragma unroll
        for (int j=0;j<8;j++) acc[i][j]=0.f;

    const int nT = K / BK;

    #pragma unroll
    for (int i=0;i<2;i++){
        long off = abase + (akq + i*2)*4;
        float4 v = *(const float4*)(A + off);
        if (Ab){
            float4 w = *(const float4*)(Ab + off);
            float4 u = *(const float4*)(Ac + off);
            v.x+=w.x+u.x; v.y+=w.y+u.y; v.z+=w.z+u.z; v.w+=w.w+u.w;
        }
        ra[i]=v;
        rb[i]= bok ? *(const float4*)(B + (long)(bkk + i*8)*N + n0 + bn)
                   : make_float4(0.f,0.f,0.f,0.f);
    }
    #pragma unroll
    for (int i=0;i<2;i++){
        int kq=(akq+i*2)*4;
        As[0][kq+0][arow]=ra[i].x; As[0][kq+1][arow]=ra[i].y;
        As[0][kq+2][arow]=ra[i].z; As[0][kq+3][arow]=ra[i].w;
        *(float4*)&Bs[0][bkk+i*8][bn] = rb[i];
    }
    __syncthreads();

    int buf=0;
    for (int t=0;t<nT;t++){
        if (t+1<nT){
            int k0=(t+1)*BK;
            #pragma unroll
            for (int i=0;i<2;i++){
                long off = abase + k0 + (akq + i*2)*4;
                float4 v = *(const float4*)(A + off);
                if (Ab){
                    float4 w = *(const float4*)(Ab + off);
                    float4 u = *(const float4*)(Ac + off);
                    v.x+=w.x+u.x; v.y+=w.y+u.y; v.z+=w.z+u.z; v.w+=w.w+u.w;
                }
                ra[i]=v;
                rb[i]= bok ? *(const float4*)(B + (long)(k0 + bkk + i*8)*N + n0 + bn)
                           : make_float4(0.f,0.f,0.f,0.f);
            }
        }
        #pragma unroll
        for (int kk=0;kk<BK;kk++){
            float4 a0=*(const float4*)&As[buf][kk][ty*8];
            float4 a1=*(const float4*)&As[buf][kk][ty*8+4];
            float4 b0=*(const float4*)&Bs[buf][kk][tx*8];
            float4 b1=*(const float4*)&Bs[buf][kk][tx*8+4];
            float av[8]={a0.x,a0.y,a0.z,a0.w,a1.x,a1.y,a1.z,a1.w};
            float bv[8]={b0.x,b0.y,b0.z,b0.w,b1.x,b1.y,b1.z,b1.w};
            #pragma unroll
            for (int i=0;i<8;i++)
                #pragma unroll
                for (int j=0;j<8;j++) acc[i][j] += av[i]*bv[j];
        }
        if (t+1<nT){
            int nb=buf^1;
            #pragma unroll
            for (int i=0;i<2;i++){
                int kq=(akq+i*2)*4;
                As[nb][kq+0][arow]=ra[i].x; As[nb][kq+1][arow]=ra[i].y;
                As[nb][kq+2][arow]=ra[i].z; As[nb][kq+3][arow]=ra[i].w;
                *(float4*)&Bs[nb][bkk+i*8][bn] = rb[i];
            }
        }
        __syncthreads();
        buf^=1;
    }

    #pragma unroll
    for (int i=0;i<8;i++){
        int gm = m0 + ty*8 + i;
        #pragma unroll
        for (int j=0;j<8;j++){
            int gn = n0 + tx*8 + j;
            if (gn >= N) continue;
            float vv = acc[i][j];
            if (epi==EPI_SILU)         vv = vv/(1.f+__expf(-vv));
            else if (epi==EPI_SIGMOID) vv = 1.f/(1.f+__expf(-vv));
            if (epi==EPI_HEAD) C[((gn>>6)*S + gm)*D + (gn&63)] = vv;
            else               C[(long)gm*N + gn] = vv;
        }
    }
}

// ---------------- compression Phi (rewritten) ----------------
// One level: b[p][d] = silu(sum_j a[p][j] * W[j][d]), a rows contiguous [P][128].
template<int P>
__device__ __forceinline__ void phi_level(const float* __restrict__ a,
                                          float* __restrict__ b,
                                          const float* __restrict__ W, int d)
{
    float accs[P];
    #pragma unroll
    for (int p=0;p<P;p++) accs[p]=0.f;
    #pragma unroll 4
    for (int j=0;j<128;j+=4){
        float w0=W[(j+0)*64+d], w1=W[(j+1)*64+d];
        float w2=W[(j+2)*64+d], w3=W[(j+3)*64+d];
        #pragma unroll
        for (int p=0;p<P;p++){
            float4 c = *(const float4*)&a[p*128+j];
            accs[p] += c.x*w0;
            accs[p] += c.y*w1;
            accs[p] += c.z*w2;
            accs[p] += c.w*w3;
        }
    }
    #pragma unroll
    for (int p=0;p<P;p++){
        float xx = accs[p];
        b[p*64+d] = xx / (1.f + __expf(-xx));
    }
}

// grid (32, H, 2): 4 windows per 256-thread block; z=0 -> K, z=1 -> V.
__global__ __launch_bounds__(256)
void compress2(const float* __restrict__ ksrc, const float* __restrict__ vsrc,
               const float* __restrict__ pe_k, const float* __restrict__ down_k,
               const float* __restrict__ stop_k,
               const float* __restrict__ pe_v, const float* __restrict__ down_v,
               const float* __restrict__ stop_v,
               float* __restrict__ kc, float* __restrict__ vc)
{
    __shared__ __align__(16) float bufX[4*2048];
    __shared__ __align__(16) float bufY[4*1024];
    const int tid = threadIdx.x;
    const int d   = tid & 63;
    const int sub = tid >> 6;
    const int w   = blockIdx.x*4 + sub;     // 0..127
    const int h   = blockIdx.y;
    const int z   = blockIdx.z;
    const float* src  = z ? vsrc  : ksrc;
    const float* pe   = z ? pe_v  : pe_k;
    const float* down = z ? down_v: down_k;
    const float* stop = z ? stop_v: stop_k;
    float* dst        = z ? vc    : kc;

    float* X = bufX + sub*2048;
    float* Y = bufY + sub*1024;

    if (w > 0){
        int s0 = (w-1)*16;
        #pragma unroll
        for (int i=0;i<32;i++)
            X[i*64+d] = src[(h*S + s0+i)*D + d] + pe[i*64+d];
    }
    __syncthreads();

    phi_level<16>(X, Y, down,         d);  __syncthreads();
    phi_level<8> (Y, X, down + 8192,  d);  __syncthreads();
    phi_level<4> (X, Y, down + 16384, d);  __syncthreads();
    phi_level<2> (Y, X, down + 24576, d);  __syncthreads();
    phi_level<1> (X, Y, down + 32768, d);  __syncthreads();

    float a = 0.f;
    #pragma unroll
    for (int j=0;j<64;j+=4){
        float4 c = *(const float4*)&Y[j];
        a += c.x*stop[(j+0)*64+d];
        a += c.y*stop[(j+1)*64+d];
        a += c.z*stop[(j+2)*64+d];
        a += c.w*stop[(j+3)*64+d];
    }
    dst[(h*SCMP + w)*D + d] = (w > 0) ? a : 0.f;
}

// ---------------- compressed branch + conv + top-k selection ----------------
__global__ void cmp_attn(float scale)
{
    extern __shared__ float csm[];
    float* kc_s = csm;             // 8192
    float* vc_s = kc_s + 8192;     // 8192
    float* q_s  = vc_s + 8192;     // 64
    float* p_sm = q_s + 64;        // 128
    float* ps   = p_sm + 128;      // 32
    float* ps2  = ps + 32;         // 64
    float* red  = ps2 + 64;        // 4

    int h = blockIdx.y;
    int tid = threadIdx.x;
    int lane = tid & 31, wid = tid >> 5;

    for (int i=tid;i<8192;i+=128){ kc_s[i]=d_kc[h*8192+i]; vc_s[i]=d_vc[h*8192+i]; }

    for (int qi=0;qi<8;qi++){
        int q = blockIdx.x*8 + qi;
        __syncthreads();
        if (tid < 64) q_s[tid] = d_q[(h*S + q)*D + tid];
        __syncthreads();

        int r = q >> 4;
        float sc = -INFINITY;
        {
            bool ok = (tid <= r-1) || (tid==0 && r<32);
            if (ok){
                float a=0.f;
                #pragma unroll
                for (int dd=0;dd<64;dd++) a += q_s[dd]*kc_s[tid*64+dd];
                sc = a*scale;
            }
        }
        float v = sc;
        #pragma unroll
        for (int off=16;off;off>>=1) v = fmaxf(v, __shfl_xor_sync(0xffffffffu,v,off));
        if (lane==0) red[wid]=v;
        __syncthreads();
        float m = fmaxf(fmaxf(red[0],red[1]),fmaxf(red[2],red[3]));
        float p = __expf(sc - m);
        p_sm[tid] = p;
        __syncthreads();
        float sv = p;
        #pragma unroll
        for (int off=16;off;off>>=1) sv += __shfl_xor_sync(0xffffffffu,sv,off);
        if (lane==0) red[wid]=sv;
        __syncthreads();
        float l = red[0]+red[1]+red[2]+red[3];

        if (wid == 3){
            int n = lane;
            float a = 2.f*(p_sm[4*n] + p_sm[4*n+1] + p_sm[4*n+2]) + p_sm[4*n+3];
            if (4*n-1 >= 0) a += p_sm[4*n-1];
            ps[n] = a;
            __syncwarp();
            float mv = ps[n];
            int cnt = 0;
            #pragma unroll
            for (int i2=0;i2<32;i2++){
                float vi = ps[i2];
                cnt += (vi > mv) || (vi == mv && i2 < n);
            }
            bool sel = (cnt < 16) && (n < (q >> 6));
            unsigned msk = __ballot_sync(0xffffffffu, sel);
            if (lane==0) d_bm[h*S + q] = msk;
        }
        float a;
        if (tid < 64){
            a = 0.f;
            for (int j=0;j<64;j++) a += p_sm[j]*vc_s[j*64+tid];
        } else {
            float b = 0.f;
            int dd = tid - 64;
            for (int j=64;j<128;j++) b += p_sm[j]*vc_s[j*64+dd];
            ps2[dd] = b;
            a = 0.f;
        }
        __syncthreads();
        if (tid < 64){
            float g0 = d_gate[q*GDIM + h*3 + 0];
            d_o1[q*DIMM + h*64 + tid] = g0 * ((a + ps2[tid]) / l);
        }
    }
}

// ---------------- flash-style sparse attention ----------------
template<int MODE>
__global__ void attn_flash(float scale)
{
    extern __shared__ float fsm[];
    float* q_s  = fsm;
    float* kv_s = q_s  + 64*65;
    float* p_s  = kv_s + 64*65;
    float* m_s  = p_s  + 64*65;
    float* l_s  = m_s + 64;
    unsigned* msk_s = (unsigned*)(l_s + 64);
    unsigned* u_s   = msk_s + 64;

    int tq = blockIdx.x, h = blockIdx.y;
    int q0 = tq*64;
    int tid = threadIdx.x;
    int tx = tid & 15, ty = tid >> 4;

    #pragma unroll
    for (int r2=0;r2<16;r2++){
        int li = tid + r2*256;
        int row = li>>6, col = li&63;
        q_s[row*65+col] = d_q[(h*S + q0+row)*D + col];
    }
    if (tid < 64){
        m_s[tid] = -INFINITY; l_s[tid] = 0.f;
        if (MODE==0) msk_s[tid] = d_bm[h*S + q0 + tid];
    }
    __syncthreads();

    unsigned uni = 0xFFFFFFFFu;
    if (MODE==0){
        if (tid==0){
            unsigned u=0;
            for (int i=0;i<64;i++) u |= msk_s[i];
            u_s[0]=u;
        }
        __syncthreads();
        uni = u_s[0];
    }

    int nlo, nhi;
    if (MODE==0){ nlo=0; nhi=(uni==0u)?0:tq; }
    else { nlo = tq-8; if (nlo<0) nlo=0; nhi = tq+1; }

    float acc[4][4];
    #pragma unroll
    for (int i=0;i<4;i++)
        #pragma unroll
        for (int j=0;j<4;j++) acc[i][j]=0.f;

    for (int n=nlo;n<nhi;n++){
        if (MODE==0 && !((uni>>n)&1u)) continue;

        #pragma unroll
        for (int r2=0;r2<16;r2++){
            int li = tid + r2*256;
            int row = li>>6, col = li&63;
            kv_s[row*65+col] = d_k[(h*S + n*64+row)*D + col];
        }
        __syncthreads();

        float s[4][4];
        #pragma unroll
        for (int i=0;i<4;i++)
            #pragma unroll
            for (int j=0;j<4;j++) s[i][j]=0.f;
        #pragma unroll 8
        for (int dd=0;dd<64;dd++){
            float qv[4], kv[4];
            #pragma unroll
            for (int i=0;i<4;i++) qv[i]=q_s[(ty*4+i)*65 + dd];
            #pragma unroll
            for (int j=0;j<4;j++) kv[j]=kv_s[(tx*4+j)*65 + dd];
            #pragma unroll
            for (int i=0;i<4;i++)
                #pragma unroll
                for (int j=0;j<4;j++) s[i][j] += qv[i]*kv[j];
        }

        float amn[4], anl[4];
        #pragma unroll
        for (int i=0;i<4;i++){
            int qi = ty*4+i;
            int qg = q0 + qi;
            unsigned mbits = (MODE==0) ? msk_s[qi] : 0u;
            float rm = -INFINITY;
            #pragma unroll
            for (int j=0;j<4;j++){
                bool ok;
                if (MODE==0) ok = (mbits>>n)&1u;
                else { int t = n*64 + tx*4 + j; ok = (t <= qg) && (qg - t <= 512); }
                float val = ok ? s[i][j]*scale : -INFINITY;
                s[i][j]=val;
                rm = fmaxf(rm, val);
            }
            #pragma unroll
            for (int off=8;off;off>>=1) rm = fmaxf(rm, __shfl_xor_sync(0xffffffffu, rm, off));
            float mo = m_s[qi];
            float mn = fmaxf(mo, rm);
            float alpha = 1.f, ts = 0.f;
            if (mn == -INFINITY){
                #pragma unroll
                for (int j=0;j<4;j++) s[i][j]=0.f;
            } else {
                alpha = __expf(mo - mn);
                #pragma unroll
                for (int j=0;j<4;j++){ float pp = __expf(s[i][j]-mn); s[i][j]=pp; ts += pp; }
            }
            #pragma unroll
            for (int off=8;off;off>>=1) ts += __shfl_xor_sync(0xffffffffu, ts, off);
            #pragma unroll
            for (int j=0;j<4;j++) p_s[qi*65 + tx*4 + j] = s[i][j];
            #pragma unroll
            for (int j=0;j<4;j++) acc[i][j] *= alpha;
            amn[i]=mn; anl[i]=l_s[qi]*alpha + ts;
        }
        __syncthreads();
        if (tx==0){
            #pragma unroll
            for (int i=0;i<4;i++){ m_s[ty*4+i]=amn[i]; l_s[ty*4+i]=anl[i]; }
        }
        #pragma unroll
        for (int r2=0;r2<16;r2++){
            int li = tid + r2*256;
            int row = li>>6, col = li&63;
            kv_s[row*65+col] = d_v[(h*S + n*64+row)*D + col];
        }
        __syncthreads();
        #pragma unroll 4
        for (int kk=0;kk<64;kk++){
            float pv[4], vv[4];
            #pragma unroll
            for (int i=0;i<4;i++) pv[i]=p_s[(ty*4+i)*65+kk];
            #pragma unroll
            for (int j=0;j<4;j++) vv[j]=kv_s[kk*65 + tx*4 + j];
            #pragma unroll
            for (int i=0;i<4;i++)
                #pragma unroll
                for (int j=0;j<4;j++) acc[i][j] += pv[i]*vv[j];
        }
        __syncthreads();
    }

    float* outp = (MODE==0) ? d_o2 : d_o3;
    #pragma unroll
    for (int i=0;i<4;i++){
        int qg = q0 + ty*4 + i;
        float l = l_s[ty*4+i];
        float inv = (l > 0.f) ? 1.f/l : 0.f;
        float g = d_gate[qg*GDIM + h*3 + (MODE==0 ? 1 : 2)];
        #pragma unroll
        for (int j=0;j<4;j++)
            outp[qg*DIMM + h*64 + tx*4 + j] = g * acc[i][j] * inv;
    }
}

// ---------------- launch ----------------
static cudaStream_t sA = nullptr, sB = nullptr;
static cudaEvent_t e0, e_qkv, e_gate, e_cmp, e_f0, e_f1;

extern "C" void kernel_launch(void* const* d_in, const int* in_sizes, int n_in,
                              void* d_out, int out_size)
{
    (void)in_sizes; (void)n_in; (void)out_size;
    const float* x      = (const float*)d_in[0];
    const float* wq     = (const float*)d_in[1];
    const float* wk     = (const float*)d_in[2];
    const float* wv     = (const float*)d_in[3];
    const float* wo     = (const float*)d_in[4];
    const float* gw1    = (const float*)d_in[5];
    const float* gw2    = (const float*)d_in[6];
    const float* pe_k   = (const float*)d_in[7];
    const float* down_k = (const float*)d_in[8];
    const float* stop_k = (const float*)d_in[9];
    const float* pe_v   = (const float*)d_in[10];
    const float* down_v = (const float*)d_in[11];
    const float* stop_v = (const float*)d_in[12];

    if (!sA){
        cudaStreamCreateWithFlags(&sA, cudaStreamNonBlocking);
        cudaStreamCreateWithFlags(&sB, cudaStreamNonBlocking);
        cudaEventCreateWithFlags(&e0,     cudaEventDisableTiming);
        cudaEventCreateWithFlags(&e_qkv,  cudaEventDisableTiming);
        cudaEventCreateWithFlags(&e_gate, cudaEventDisableTiming);
        cudaEventCreateWithFlags(&e_cmp,  cudaEventDisableTiming);
        cudaEventCreateWithFlags(&e_f0,   cudaEventDisableTiming);
        cudaEventCreateWithFlags(&e_f1,   cudaEventDisableTiming);
        const int CSM = (8192+8192+64+128+32+64+4)*4;
        cudaFuncSetAttribute(cmp_attn, cudaFuncAttributeMaxDynamicSharedMemorySize, CSM);
        const int FSM = (3*64*65 + 64 + 64)*4 + 65*4;
        cudaFuncSetAttribute(attn_flash<0>, cudaFuncAttributeMaxDynamicSharedMemorySize, FSM);
        cudaFuncSetAttribute(attn_flash<1>, cudaFuncAttributeMaxDynamicSharedMemorySize, FSM);
    }

    float *q_p, *k_p, *v_p, *g1_p, *gate_p, *kc_p, *vc_p, *o1_p, *o2_p, *o3_p;
    cudaGetSymbolAddress((void**)&q_p,    d_q);
    cudaGetSymbolAddress((void**)&k_p,    d_k);
    cudaGetSymbolAddress((void**)&v_p,    d_v);
    cudaGetSymbolAddress((void**)&g1_p,   d_g1);
    cudaGetSymbolAddress((void**)&gate_p, d_gate);
    cudaGetSymbolAddress((void**)&kc_p,   d_kc);
    cudaGetSymbolAddress((void**)&vc_p,   d_vc);
    cudaGetSymbolAddress((void**)&o1_p,   d_o1);
    cudaGetSymbolAddress((void**)&o2_p,   d_o2);
    cudaGetSymbolAddress((void**)&o3_p,   d_o3);

    const float scale = 0.125f;
    const int CSM = (8192+8192+64+128+32+64+4)*4;
    const int FSM = (3*64*65 + 64 + 64)*4 + 65*4;

    cudaEventRecord(e0, 0);
    cudaStreamWaitEvent(sA, e0, 0);

    // stream0: fused QKV projection
    gemm_big<<<dim3(8,16,3),256>>>(x, nullptr, nullptr, wq, wk, wv,
                                   q_p, k_p, v_p, S, 1024, DIMM, EPI_HEAD);
    cudaEventRecord(e_qkv, 0);

    // sA: gate chain
    gemm_big<<<dim3(4,16,1),256,0,sA>>>(x, nullptr, nullptr, gw1, gw1, gw1,
                                        g1_p, g1_p, g1_p, S, 512, DIMM, EPI_SILU);
    gemm_big<<<dim3(1,16,1),256,0,sA>>>(g1_p, nullptr, nullptr, gw2, gw2, gw2,
                                        gate_p, gate_p, gate_p, S, GDIM, 512, EPI_SIGMOID);
    cudaEventRecord(e_gate, sA);

    // stream0: fused K+V compression, then compressed branch (+ masks)
    compress2<<<dim3(32,16,2),256>>>(k_p, v_p, pe_k, down_k, stop_k,
                                     pe_v, down_v, stop_v, kc_p, vc_p);
    cudaStreamWaitEvent(0, e_gate, 0);
    cmp_attn<<<dim3(S/8,16),128,CSM>>>(scale);
    cudaEventRecord(e_cmp, 0);

    // sA: sliding-window branch
    cudaStreamWaitEvent(sA, e_qkv, 0);
    attn_flash<1><<<dim3(S/64,16),256,FSM,sA>>>(scale);
    cudaEventRecord(e_f1, sA);

    // sB: selection branch (needs masks + gate)
    cudaStreamWaitEvent(sB, e_cmp, 0);
    cudaStreamWaitEvent(sB, e_gate, 0);
    attn_flash<0><<<dim3(S/64,16),256,FSM,sB>>>(scale);
    cudaEventRecord(e_f0, sB);

    // join + output projection
    cudaStreamWaitEvent(0, e_f1, 0);
    cudaStreamWaitEvent(0, e_f0, 0);
    gemm_big<<<dim3(8,16,1),256>>>(o1_p, o2_p, o3_p, wo, wo, wo,
                                   (float*)d_out, (float*)d_out, (float*)d_out,
                                   S, DIMM, DIMM, EPI_NONE);
}